// round 1
// baseline (speedup 1.0000x reference)
#include <cuda_runtime.h>
#include <math.h>

// ---------------- problem constants ----------------
#define Bsz 16
#define Nn  1024
#define Cin 2
#define Tt  12
#define HIDc 64
#define T1  10          // T-2
#define T2n 8           // T-4
#define OC  384         // OUT*PRED
#define Ee  16384
#define BT1 (Bsz*T1)    // 160
#define K2  192         // HID*KT for conv2
#define STAT_CNT 49152.0f  // B*T2n*OC per-node BN count

// ---------------- device scratch (static, no allocs) ----------------
__device__ float g_T0 [Nn*BT1*HIDc];   // (n, b*10+t, h)
__device__ float g_Tx1[Nn*BT1*HIDc];
__device__ float g_Tx2[Nn*BT1*HIDc];
__device__ float g_Tg [Nn*BT1*HIDc];
__device__ float g_last[Bsz*Nn*OC];    // (b*Nn+n)*OC + o  (t''=7 slice, pre-BN)
__device__ float g_wt [3*K2*OC];       // transposed conv2 weights: [s][k][o]
__device__ float g_deg[Nn];
__device__ float g_dinv[Nn];
__device__ int   g_cntv[Nn];
__device__ int   g_indptr[Nn];
__device__ int   g_counter[Nn];
__device__ int   g_csr_row[Ee];
__device__ float g_csr_nrm[Ee];
__device__ float g_sum[Nn];
__device__ float g_sumsq[Nn];

// ---------------- init: zero per-launch state ----------------
__global__ void k_init() {
    int i = threadIdx.x;                 // 1024 threads, 1 block
    g_deg[i] = 0.f; g_cntv[i] = 0; g_counter[i] = 0;
    g_sum[i] = 0.f; g_sumsq[i] = 0.f;
}

// ---------------- degree + per-dest count ----------------
__global__ void k_deg(const int* __restrict__ ei, const float* __restrict__ ew) {
    int e = blockIdx.x * blockDim.x + threadIdx.x;
    if (e >= Ee) return;
    int r = ei[e], c = ei[Ee + e];
    if (r != c) atomicAdd(&g_deg[r], ew[e]);
    atomicAdd(&g_cntv[c], 1);
}

// ---------------- dinv + exclusive scan of counts ----------------
__global__ void k_scan() {
    __shared__ int s[Nn];
    int t = threadIdx.x;                 // 1024 threads
    float d = g_deg[t];
    g_dinv[t] = (d > 0.f) ? rsqrtf(d) : 0.f;
    int c = g_cntv[t];
    s[t] = c;
    __syncthreads();
    for (int off = 1; off < Nn; off <<= 1) {
        int v = (t >= off) ? s[t - off] : 0;
        __syncthreads();
        s[t] += v;
        __syncthreads();
    }
    g_indptr[t] = s[t] - c;              // exclusive prefix
}

// ---------------- scatter edges into CSR (by destination) ----------------
__global__ void k_scatter(const int* __restrict__ ei, const float* __restrict__ ew) {
    int e = blockIdx.x * blockDim.x + threadIdx.x;
    if (e >= Ee) return;
    int r = ei[e], c = ei[Ee + e];
    float nm = (r == c) ? 0.f : -(g_dinv[r] * ew[e] * g_dinv[c]);
    int pos = g_indptr[c] + atomicAdd(&g_counter[c], 1);
    g_csr_row[pos] = r;
    g_csr_nrm[pos] = nm;
}

// ---------------- temporal conv 1 (C=2 -> 64, gated GLU) ----------------
// grid: Bsz*Nn blocks, 64 threads (h). Output layout (n, b*10+t', h).
__global__ __launch_bounds__(64) void k_conv1(
    const float* __restrict__ X,
    const float* __restrict__ w1, const float* __restrict__ b1,
    const float* __restrict__ w2, const float* __restrict__ b2,
    const float* __restrict__ w3, const float* __restrict__ b3)
{
    int bid = blockIdx.x;
    int n = bid >> 4, b = bid & 15;
    int h = threadIdx.x;
    __shared__ float sx[2][12];
    if (h < 24) {
        int c = h / 12, t = h % 12;
        sx[c][t] = X[((b * Nn + n) * 2 + c) * 12 + t];
    }
    float w1r[6], w2r[6], w3r[6];
#pragma unroll
    for (int j = 0; j < 6; j++) {
        w1r[j] = w1[h * 6 + j];
        w2r[j] = w2[h * 6 + j];
        w3r[j] = w3[h * 6 + j];
    }
    float bb1 = b1[h], bb2 = b2[h], bb3 = b3[h];
    __syncthreads();
#pragma unroll
    for (int tp = 0; tp < T1; tp++) {
        float P = bb1, Q = bb2, R = bb3;
#pragma unroll
        for (int c = 0; c < 2; c++)
#pragma unroll
            for (int k = 0; k < 3; k++) {
                float v = sx[c][tp + k];
                P += v * w1r[c * 3 + k];
                Q += v * w2r[c * 3 + k];
                R += v * w3r[c * 3 + k];
            }
        float sg = 1.f / (1.f + expf(-Q));
        float val = P * sg + R;
        val = val > 0.f ? val : 0.f;
        g_T0[(n * BT1 + b * T1 + tp) * HIDc + h] = val;
    }
}

// ---------------- conv2 weight transpose: [s][k=(dt*64+h)][o] ----------------
__global__ void k_wtrans(const float* __restrict__ w1,
                         const float* __restrict__ w2,
                         const float* __restrict__ w3)
{
    int idx = blockIdx.x * blockDim.x + threadIdx.x;
    if (idx >= 3 * K2 * OC) return;
    int s = idx / (K2 * OC);
    int r = idx % (K2 * OC);
    int k = r / OC, o = r % OC;
    int h = k & 63, dt = k >> 6;
    const float* w = (s == 0) ? w1 : (s == 1) ? w2 : w3;
    g_wt[idx] = w[(o * HIDc + h) * 3 + dt];
}

// ---------------- graph propagation (gather CSR) ----------------
// mode 0: Tx1 = L_hat @ T0          (out=g_Tx1, z=g_T0)
// mode 1: Tx2 = 2*(L_hat @ Tx1) - T0 (out=g_Tx2, z=g_Tx1)
__global__ __launch_bounds__(256) void k_prop(int mode) {
    const float* __restrict__ z = (mode == 0) ? g_T0 : g_Tx1;
    float* __restrict__ out = (mode == 0) ? g_Tx1 : g_Tx2;
    int j = blockIdx.x;
    int tid = threadIdx.x;
    int hq = tid & 15;            // h = hq*4
    int g = tid >> 4;             // 16 groups, 10 bt each
    float4 acc[10];
#pragma unroll
    for (int i = 0; i < 10; i++) acc[i] = make_float4(0.f, 0.f, 0.f, 0.f);

    int start = g_indptr[j], cnt = g_cntv[j];
    __shared__ int sr[64];
    __shared__ float sn[64];
    for (int eb = 0; eb < cnt; eb += 64) {
        int m = cnt - eb; if (m > 64) m = 64;
        if (tid < m) { sr[tid] = g_csr_row[start + eb + tid]; sn[tid] = g_csr_nrm[start + eb + tid]; }
        __syncthreads();
        for (int e = 0; e < m; e++) {
            int r = sr[e];
            float nm = sn[e];
            const float4* zp = (const float4*)z + (size_t)(r * BT1 + g * 10) * 16 + hq;
#pragma unroll
            for (int i = 0; i < 10; i++) {
                float4 v = zp[(size_t)i * 16];
                acc[i].x += nm * v.x; acc[i].y += nm * v.y;
                acc[i].z += nm * v.z; acc[i].w += nm * v.w;
            }
        }
        __syncthreads();
    }
    float4* op = (float4*)out + (size_t)(j * BT1 + g * 10) * 16 + hq;
    if (mode == 0) {
#pragma unroll
        for (int i = 0; i < 10; i++) op[(size_t)i * 16] = acc[i];
    } else {
        const float4* sp = (const float4*)g_T0 + (size_t)(j * BT1 + g * 10) * 16 + hq;
#pragma unroll
        for (int i = 0; i < 10; i++) {
            float4 s0 = sp[(size_t)i * 16];
            float4 o4;
            o4.x = 2.f * acc[i].x - s0.x; o4.y = 2.f * acc[i].y - s0.y;
            o4.z = 2.f * acc[i].z - s0.z; o4.w = 2.f * acc[i].w - s0.w;
            op[(size_t)i * 16] = o4;
        }
    }
}

// ---------------- cheb combine: Tg = relu(T0@W0 + Tx1@W1 + Tx2@W2 + b) ----------------
// grid 2560, 256 threads, 64x64 tile, K=3*64
__global__ __launch_bounds__(256) void k_chebmm(const float* __restrict__ chebW,
                                               const float* __restrict__ chebB)
{
    __shared__ float As[64][17];
    __shared__ __align__(16) float Bs[16][64];
    int m0 = blockIdx.x * 64;
    int tid = threadIdx.x;
    int tx = tid & 15, ty = tid >> 4;       // f = tx*4.., m = ty*4..
    float acc[4][4];
#pragma unroll
    for (int i = 0; i < 4; i++)
#pragma unroll
        for (int jj = 0; jj < 4; jj++) acc[i][jj] = 0.f;

    const float* srcs[3] = { g_T0, g_Tx1, g_Tx2 };
    int lkk = tid & 15, lmi = tid >> 4;     // A loader
    int lo = tid & 63, lkq = tid >> 6;      // B loader

    for (int s = 0; s < 3; s++) {
        const float* A = srcs[s];
        const float* W = chebW + s * (HIDc * HIDc);
        for (int kc = 0; kc < 4; kc++) {
#pragma unroll
            for (int p = 0; p < 4; p++)
                As[lmi + 16 * p][lkk] = A[(size_t)(m0 + lmi + 16 * p) * HIDc + kc * 16 + lkk];
#pragma unroll
            for (int p = 0; p < 4; p++)
                Bs[lkq + 4 * p][lo] = W[(kc * 16 + lkq + 4 * p) * HIDc + lo];
            __syncthreads();
#pragma unroll
            for (int kk = 0; kk < 16; kk++) {
                float a[4];
#pragma unroll
                for (int i = 0; i < 4; i++) a[i] = As[ty * 4 + i][kk];
                float4 bv = *(const float4*)&Bs[kk][tx * 4];
#pragma unroll
                for (int i = 0; i < 4; i++) {
                    acc[i][0] += a[i] * bv.x; acc[i][1] += a[i] * bv.y;
                    acc[i][2] += a[i] * bv.z; acc[i][3] += a[i] * bv.w;
                }
            }
            __syncthreads();
        }
    }
    float bb[4];
#pragma unroll
    for (int jj = 0; jj < 4; jj++) bb[jj] = chebB[tx * 4 + jj];
#pragma unroll
    for (int i = 0; i < 4; i++) {
        int m = m0 + ty * 4 + i;
        float4 o4;
        float v0 = acc[i][0] + bb[0]; o4.x = v0 > 0.f ? v0 : 0.f;
        float v1 = acc[i][1] + bb[1]; o4.y = v1 > 0.f ? v1 : 0.f;
        float v2 = acc[i][2] + bb[2]; o4.z = v2 > 0.f ? v2 : 0.f;
        float v3 = acc[i][3] + bb[3]; o4.w = v3 > 0.f ? v3 : 0.f;
        *(float4*)&g_Tg[(size_t)m * HIDc + tx * 4] = o4;
    }
}

// ---------------- temporal conv 2 (64 -> 384, gated) + BN stats + last slice ----------------
// grid (12, 1024): o-tile x node. 128 threads, BM=128 (all b,t''), BO=32, K=192, 3 weight sets.
__global__ __launch_bounds__(128) void k_conv2(
    const float* __restrict__ b1, const float* __restrict__ b2, const float* __restrict__ b3)
{
    __shared__ float As[16][129];                 // [kk][m]
    __shared__ __align__(16) float Bs[3][16][32]; // [s][kk][o]
    int n = blockIdx.y;
    int o0 = blockIdx.x * 32;
    int tid = threadIdx.x;
    int tx = tid & 7, ty = tid >> 3;              // o = o0+tx*4.., m = ty+16p

    float4 accP[8], accQ[8], accR[8];
#pragma unroll
    for (int p = 0; p < 8; p++) {
        accP[p] = make_float4(0.f, 0.f, 0.f, 0.f);
        accQ[p] = make_float4(0.f, 0.f, 0.f, 0.f);
        accR[p] = make_float4(0.f, 0.f, 0.f, 0.f);
    }

    int lkk = tid & 15, lm = tid >> 4;            // A loader: 8 m per pass
    int lo = tid & 31, lk = tid >> 5;             // B loader

    for (int kc = 0; kc < 12; kc++) {
        int dt = kc >> 2;
        int hbase = (kc & 3) * 16;
#pragma unroll
        for (int p = 0; p < 16; p++) {
            int m = lm + 8 * p;
            int rowg = (m >> 3) * T1 + (m & 7) + dt;
            As[lkk][m] = g_Tg[(size_t)(n * BT1 + rowg) * HIDc + hbase + lkk];
        }
#pragma unroll
        for (int s = 0; s < 3; s++)
#pragma unroll
            for (int p = 0; p < 4; p++) {
                int kk = lk + 4 * p;
                Bs[s][kk][lo] = g_wt[(size_t)s * (K2 * OC) + (size_t)(dt * 64 + hbase + kk) * OC + o0 + lo];
            }
        __syncthreads();
#pragma unroll
        for (int kk = 0; kk < 16; kk++) {
            float a[8];
#pragma unroll
            for (int p = 0; p < 8; p++) a[p] = As[kk][ty + 16 * p];
            float4 b1v = *(const float4*)&Bs[0][kk][tx * 4];
            float4 b2v = *(const float4*)&Bs[1][kk][tx * 4];
            float4 b3v = *(const float4*)&Bs[2][kk][tx * 4];
#pragma unroll
            for (int p = 0; p < 8; p++) {
                accP[p].x += a[p] * b1v.x; accP[p].y += a[p] * b1v.y;
                accP[p].z += a[p] * b1v.z; accP[p].w += a[p] * b1v.w;
                accQ[p].x += a[p] * b2v.x; accQ[p].y += a[p] * b2v.y;
                accQ[p].z += a[p] * b2v.z; accQ[p].w += a[p] * b2v.w;
                accR[p].x += a[p] * b3v.x; accR[p].y += a[p] * b3v.y;
                accR[p].z += a[p] * b3v.z; accR[p].w += a[p] * b3v.w;
            }
        }
        __syncthreads();
    }

    float bb1[4], bb2[4], bb3[4];
#pragma unroll
    for (int jj = 0; jj < 4; jj++) {
        bb1[jj] = b1[o0 + tx * 4 + jj];
        bb2[jj] = b2[o0 + tx * 4 + jj];
        bb3[jj] = b3[o0 + tx * 4 + jj];
    }
    float lsum = 0.f, lss = 0.f;
#pragma unroll
    for (int p = 0; p < 8; p++) {
        int bt2 = ty + 16 * p;
        int bb = bt2 >> 3, t2 = bt2 & 7;
        float vals[4];
        float Pv[4] = { accP[p].x, accP[p].y, accP[p].z, accP[p].w };
        float Qv[4] = { accQ[p].x, accQ[p].y, accQ[p].z, accQ[p].w };
        float Rv[4] = { accR[p].x, accR[p].y, accR[p].z, accR[p].w };
#pragma unroll
        for (int jj = 0; jj < 4; jj++) {
            float P = Pv[jj] + bb1[jj];
            float Q = Qv[jj] + bb2[jj];
            float R = Rv[jj] + bb3[jj];
            float sg = 1.f / (1.f + expf(-Q));
            float v = P * sg + R;
            v = v > 0.f ? v : 0.f;
            vals[jj] = v;
            lsum += v;
            lss += v * v;
        }
        if (t2 == 7) {
            float4 vv = make_float4(vals[0], vals[1], vals[2], vals[3]);
            *(float4*)&g_last[(size_t)(bb * Nn + n) * OC + o0 + tx * 4] = vv;
        }
    }
    // block reduce -> 2 atomics
    unsigned lane = tid & 31, warp = tid >> 5;
#pragma unroll
    for (int off = 16; off > 0; off >>= 1) {
        lsum += __shfl_down_sync(0xffffffffu, lsum, off);
        lss  += __shfl_down_sync(0xffffffffu, lss,  off);
    }
    __shared__ float wsum[4], wss[4];
    if (lane == 0) { wsum[warp] = lsum; wss[warp] = lss; }
    __syncthreads();
    if (tid == 0) {
        atomicAdd(&g_sum[n],   wsum[0] + wsum[1] + wsum[2] + wsum[3]);
        atomicAdd(&g_sumsq[n], wss[0] + wss[1] + wss[2] + wss[3]);
    }
}

// ---------------- final: BN + transpose to output ----------------
// grid 16384 (b*1024+n), 384 threads (cout)
__global__ __launch_bounds__(384) void k_final(
    const float* __restrict__ gamma, const float* __restrict__ beta,
    float* __restrict__ out)
{
    int bid = blockIdx.x;
    int b = bid >> 10, n = bid & 1023;
    int c = threadIdx.x;
    float mean = g_sum[n] / STAT_CNT;
    float var = g_sumsq[n] / STAT_CNT - mean * mean;
    float inv = rsqrtf(var + 1e-5f);
    float ga = gamma[n], be = beta[n];
    float v = g_last[(size_t)bid * OC + c];
    out[(size_t)c * (Bsz * Nn) + b * Nn + n] = (v - mean) * inv * ga + be;
}

// ---------------- launch ----------------
extern "C" void kernel_launch(void* const* d_in, const int* in_sizes, int n_in,
                              void* d_out, int out_size)
{
    const float* X        = (const float*)d_in[0];
    const int*   ei       = (const int*)  d_in[1];
    const float* ew       = (const float*)d_in[2];
    const float* tc1_w1   = (const float*)d_in[3];
    const float* tc1_b1   = (const float*)d_in[4];
    const float* tc1_w2   = (const float*)d_in[5];
    const float* tc1_b2   = (const float*)d_in[6];
    const float* tc1_w3   = (const float*)d_in[7];
    const float* tc1_b3   = (const float*)d_in[8];
    const float* cheb_W   = (const float*)d_in[9];
    const float* cheb_b   = (const float*)d_in[10];
    const float* tc2_w1   = (const float*)d_in[11];
    const float* tc2_b1   = (const float*)d_in[12];
    const float* tc2_w2   = (const float*)d_in[13];
    const float* tc2_b2   = (const float*)d_in[14];
    const float* tc2_w3   = (const float*)d_in[15];
    const float* tc2_b3   = (const float*)d_in[16];
    const float* bn_gamma = (const float*)d_in[17];
    const float* bn_beta  = (const float*)d_in[18];
    float* out = (float*)d_out;

    k_init<<<1, 1024>>>();
    k_deg<<<Ee / 256, 256>>>(ei, ew);
    k_scan<<<1, 1024>>>();
    k_scatter<<<Ee / 256, 256>>>(ei, ew);
    k_conv1<<<Bsz * Nn, 64>>>(X, tc1_w1, tc1_b1, tc1_w2, tc1_b2, tc1_w3, tc1_b3);
    k_wtrans<<<(3 * K2 * OC + 255) / 256, 256>>>(tc2_w1, tc2_w2, tc2_w3);
    k_prop<<<Nn, 256>>>(0);
    k_prop<<<Nn, 256>>>(1);
    k_chebmm<<<(Nn * BT1) / 64, 256>>>(cheb_W, cheb_b);
    k_conv2<<<dim3(12, Nn), 128>>>(tc2_b1, tc2_b2, tc2_b3);
    k_final<<<Bsz * Nn, 384>>>(bn_gamma, bn_beta, out);
}